// round 6
// baseline (speedup 1.0000x reference)
#include <cuda_runtime.h>
#include <cuda_fp16.h>
#include <math.h>

#define NN 6000
#define EE 100000
#define NB 148          // persistent-kernel block count (co-resident on 148+ SMs)

typedef unsigned long long ull;

// ---------------- f32x2 packed helpers (sm_103a) --------------------------------
__device__ __forceinline__ void fma2(ull& d, ull a, ull b) {
    asm("fma.rn.f32x2 %0, %1, %2, %0;" : "+l"(d) : "l"(a), "l"(b));
}
__device__ __forceinline__ void add2(ull& d, ull a) {
    asm("add.rn.f32x2 %0, %0, %1;" : "+l"(d) : "l"(a));
}
__device__ __forceinline__ ull pack2(float lo, float hi) {
    ull r; asm("mov.b64 %0, {%1, %2};" : "=l"(r) : "f"(lo), "f"(hi)); return r;
}
__device__ __forceinline__ float2 unpack2(ull v) {
    float2 r; asm("mov.b64 {%0, %1}, %2;" : "=f"(r.x), "=f"(r.y) : "l"(v)); return r;
}

// ---------------- scratch (device globals; no allocations allowed) -------------
__device__ float  g_W0[2 * NN * 32];
__device__ float  g_Ha[2 * NN * 64];
__device__ float  g_Hb[2 * NN * 64];
__device__ float  g_baseA[NN * 64];
__device__ float  g_baseB[NN * 64];
__device__ float  g_Wr1[2 * 32 * 64];
__device__ float  g_Wr2[2 * 64 * 64];
__device__ float  g_Wr3[2 * 64 * 32];
__device__ __half g_h[NN * 512];       // GAT projected features (fp16)
__device__ float  g_xg[NN * 512];      // GAT output
__device__ float  g_ab[NN * 256];      // [A | B] for edge MLP
__device__ float  g_asv[NN];
__device__ float  g_adv[NN];
__device__ float  g_ps[32];
__device__ float  g_pd[32];
__device__ float  g_inv0[NN];
__device__ float  g_inv1[NN];
__device__ int    g_deg[NN];
__device__ int    g_cnt0[NN];
__device__ int    g_rowptr[NN + 1];
__device__ int    g_mid[NN];
__device__ int    g_cursor0[NN];
__device__ int    g_cursor1[NN];
__device__ int    g_cval[EE];          // rel*NN + src (rel-sorted within node)
__device__ int    g_bar_count;
__device__ int    g_bar_gen;

// ---------------- software grid barrier ------------------------------------------
__device__ __forceinline__ void grid_barrier() {
    __syncthreads();
    if (threadIdx.x == 0) {
        int gen = atomicAdd(&g_bar_gen, 0);
        __threadfence();
        if (atomicAdd(&g_bar_count, 1) == NB - 1) {
            g_bar_count = 0;
            __threadfence();
            atomicAdd(&g_bar_gen, 1);
        } else {
            while (atomicAdd(&g_bar_gen, 0) == gen) __nanosleep(64);
        }
    }
    __syncthreads();
}

// ---------------- persistent: prep + count + scan + fill ------------------------
#define SEG_W0   384000
#define SEG_WR1  (SEG_W0 + 4096)
#define SEG_WR2  (SEG_WR1 + 8192)
#define SEG_WR3  (SEG_WR2 + 4096)
#define SEG_DEG  (SEG_WR3 + 12288)     // deg[6000] + cnt0[6000]
#define SEG_PSPD (SEG_DEG + 2048)

__global__ __launch_bounds__(256) void csr_prep_kernel(
    const float* __restrict__ basis0, const float* __restrict__ comp0,
    const float* __restrict__ basis1, const float* __restrict__ comp1,
    const float* __restrict__ basis2, const float* __restrict__ comp2,
    const float* __restrict__ basis3, const float* __restrict__ comp3,
    const float* __restrict__ gw, const float* __restrict__ a_s,
    const float* __restrict__ a_d,
    const int* __restrict__ ei, const int* __restrict__ et,
    float* __restrict__ W0, float* __restrict__ Wr1,
    float* __restrict__ Wr2, float* __restrict__ Wr3,
    int* __restrict__ deg, int* __restrict__ cnt0,
    int* __restrict__ rowptr, int* __restrict__ mid,
    int* __restrict__ cursor0, int* __restrict__ cursor1,
    float* __restrict__ inv0, float* __restrict__ inv1,
    int* __restrict__ cval, float* __restrict__ ps, float* __restrict__ pd) {
    const int tid = threadIdx.x;
    const int gtid = blockIdx.x * 256 + tid;
    const int gstride = NB * 256;

    // ---- phase 0: prep ----
    for (int idx = gtid; idx < SEG_PSPD; idx += gstride) {
        int i = idx;
        if (i < SEG_W0) {
            int r = i / 192000, io = i - r * 192000;
            float s = 0.f;
#pragma unroll
            for (int b = 0; b < 4; b++) s += comp0[r * 4 + b] * basis0[b * 192000 + io];
            W0[i] = s;
        } else if (i < SEG_WR1) {
            i -= SEG_W0;
            int r = i / 2048, io = i - r * 2048;
            float s = 0.f;
#pragma unroll
            for (int b = 0; b < 4; b++) s += comp1[r * 4 + b] * basis1[b * 2048 + io];
            Wr1[i] = s;
        } else if (i < SEG_WR2) {
            i -= SEG_WR1;
            int r = i / 4096, io = i - r * 4096;
            float s = 0.f;
#pragma unroll
            for (int b = 0; b < 4; b++) s += comp2[r * 4 + b] * basis2[b * 4096 + io];
            Wr2[i] = s;
        } else if (i < SEG_WR3) {
            i -= SEG_WR2;
            int r = i / 2048, io = i - r * 2048;
            float s = 0.f;
#pragma unroll
            for (int b = 0; b < 4; b++) s += comp3[r * 4 + b] * basis3[b * 2048 + io];
            Wr3[i] = s;
        } else if (i < SEG_DEG) {
            i -= SEG_WR3;
            if (i < NN) deg[i] = 0;
            else if (i < 2 * NN) cnt0[i - NN] = 0;
        } else {
            i -= SEG_DEG;
            int w = i >> 5, lane = i & 31;
            int row = w & 31;
            const float* a = (w < 32) ? a_s : a_d;
            float s = 0.f;
            for (int c = lane; c < 512; c += 32) s += gw[row * 512 + c] * a[c];
#pragma unroll
            for (int off = 16; off > 0; off >>= 1) s += __shfl_down_sync(0xffffffffu, s, off);
            if (lane == 0) { if (w < 32) ps[row] = s; else pd[row] = s; }
        }
    }
    grid_barrier();

    // ---- phase 1: count in-degrees (total + rel0) ----
    for (int e = gtid; e < EE; e += gstride) {
        int d = ei[EE + e];
        atomicAdd(&deg[d], 1);
        if (et[e] == 0) atomicAdd(&cnt0[d], 1);
    }
    grid_barrier();

    // ---- phase 2: exclusive scan + mid/cursors/inv (block 0) ----
    if (blockIdx.x == 0) {
        int base = tid * 24;
        int loc[24];
        int sum = 0;
#pragma unroll
        for (int i = 0; i < 24; i++) {
            int idx = base + i;
            int v = (idx < NN) ? deg[idx] : 0;
            loc[i] = sum;
            sum += v;
        }
        int lane = tid & 31, w = tid >> 5;
        int v = sum;
#pragma unroll
        for (int off = 1; off < 32; off <<= 1) {
            int n = __shfl_up_sync(0xffffffffu, v, off);
            if (lane >= off) v += n;
        }
        __shared__ int wsum[8];
        __shared__ int stotal;
        if (lane == 31) wsum[w] = v;
        __syncthreads();
        if (tid == 0) {
            int run = 0;
#pragma unroll
            for (int j = 0; j < 8; j++) { int t = wsum[j]; wsum[j] = run; run += t; }
            stotal = run;
        }
        __syncthreads();
        int incl = v + wsum[w];
        int excl = incl - sum;
#pragma unroll
        for (int i = 0; i < 24; i++) {
            int idx = base + i;
            if (idx < NN) {
                int start = excl + loc[i];
                int c0 = cnt0[idx];
                int dg = deg[idx];
                rowptr[idx] = start;
                mid[idx] = start + c0;
                cursor0[idx] = start;
                cursor1[idx] = start + c0;
                inv0[idx] = 1.f / fmaxf((float)c0, 1.f);
                inv1[idx] = 1.f / fmaxf((float)(dg - c0), 1.f);
            }
        }
        if (tid == 0) rowptr[NN] = stotal;
    }
    grid_barrier();

    // ---- phase 3: fill (rel-sorted, precomputed gather index) ----
    for (int e = gtid; e < EE; e += gstride) {
        int s = ei[e];
        int d = ei[EE + e];
        int t = et[e];
        int pos = atomicAdd(t ? &cursor1[d] : &cursor0[d], 1);
        cval[pos] = t * NN + s;
    }
}

// ---------------- aggregation range helpers -------------------------------------
// f32x2 sum of Hin[cval[e]*IN + 2*k2 .. +1] over [e0,e1)
template<int IN>
__device__ __forceinline__ ull agg_range2(const float* __restrict__ Hin,
                                          const int* __restrict__ cval,
                                          int e0, int e1, int k2) {
    ull acc = 0;
    int e = e0;
    for (; e + 4 <= e1; e += 4) {
        int o0 = cval[e], o1 = cval[e + 1], o2 = cval[e + 2], o3 = cval[e + 3];
        ull v0 = *(const ull*)(Hin + o0 * IN + 2 * k2);
        ull v1 = *(const ull*)(Hin + o1 * IN + 2 * k2);
        ull v2 = *(const ull*)(Hin + o2 * IN + 2 * k2);
        ull v3 = *(const ull*)(Hin + o3 * IN + 2 * k2);
        add2(v0, v1); add2(v2, v3); add2(acc, v0); add2(acc, v2);
    }
    for (; e < e1; e++) {
        ull v = *(const ull*)(Hin + cval[e] * IN + 2 * k2);
        add2(acc, v);
    }
    return acc;
}

// scalar sum for IN=32 rows
__device__ __forceinline__ float agg_range1(const float* __restrict__ Hin,
                                            const int* __restrict__ cval,
                                            int e0, int e1, int k) {
    float a = 0.f, b = 0.f, c = 0.f, d = 0.f;
    int e = e0;
    for (; e + 4 <= e1; e += 4) {
        a += Hin[cval[e] * 32 + k];
        b += Hin[cval[e + 1] * 32 + k];
        c += Hin[cval[e + 2] * 32 + k];
        d += Hin[cval[e + 3] * 32 + k];
    }
    for (; e < e1; e++) a += Hin[cval[e] * 32 + k];
    return (a + b) + (c + d);
}

// ---------------- fused agg(L) + dense(L+1) ------------------------------------
// Block: 512 threads = 16 warps, M=16 nodes, warp per node in phase 1.
template<int IN, int OUT>
__global__ __launch_bounds__(512) void fused_agg_dense(
    const float* __restrict__ Hin, const float* __restrict__ basein,
    const float* __restrict__ bias,
    const int* __restrict__ rowptr, const int* __restrict__ mid,
    const float* __restrict__ inv0, const float* __restrict__ inv1,
    const int* __restrict__ cval,
    const float* __restrict__ Wr, const float* __restrict__ root,
    float* __restrict__ Hout, float* __restrict__ baseout) {
    constexpr int M = 16;
    __shared__ __align__(16) float xsT[IN][M];
    __shared__ __align__(16) float wsh[2 * IN * OUT];
    const int tid = threadIdx.x;
    const int wid = tid >> 5, lane = tid & 31;
    const int n0 = blockIdx.x * M;

    for (int i = tid; i < 2 * IN * OUT; i += 512) wsh[i] = Wr[i];

    // phase 1: warp-per-node aggregation (rel-sorted ranges)
    {
        int n = n0 + wid;
        int e0 = rowptr[n], em = mid[n], e1 = rowptr[n + 1];
        float i0 = inv0[n], i1 = inv1[n];
        if constexpr (IN == 64) {
            ull s0 = agg_range2<64>(Hin, cval, e0, em, lane);
            ull s1 = agg_range2<64>(Hin, cval, em, e1, lane);
            float2 a0 = unpack2(s0), a1 = unpack2(s1);
            float2 b = *(const float2*)(basein + n * 64 + 2 * lane);
            float2 bi = *(const float2*)(bias + 2 * lane);
            xsT[2 * lane][wid]     = tanhf(b.x + bi.x + a0.x * i0 + a1.x * i1);
            xsT[2 * lane + 1][wid] = tanhf(b.y + bi.y + a0.y * i0 + a1.y * i1);
        } else {
            float a0 = agg_range1(Hin, cval, e0, em, lane);
            float a1 = agg_range1(Hin, cval, em, e1, lane);
            xsT[lane][wid] = tanhf(basein[n * 32 + lane] + bias[lane] + a0 * i0 + a1 * i1);
        }
    }
    __syncthreads();

    // phase 2: dense GEMM for next layer
    constexpr int G = 512 / OUT;
    const int o = tid % OUT;
    const int g = tid / OUT;
    if constexpr (M / G == 2) {
        // pair mode (OUT=64)
        ull a0 = 0, a1 = 0, ar = 0;
        for (int i = 0; i < IN; i++) {
            float w0 = wsh[i * OUT + o];
            float w1 = wsh[IN * OUT + i * OUT + o];
            float wr = __ldg(&root[i * OUT + o]);
            ull xp = *(const ull*)&xsT[i][2 * g];
            fma2(a0, xp, pack2(w0, w0));
            fma2(a1, xp, pack2(w1, w1));
            fma2(ar, xp, pack2(wr, wr));
        }
        int n = n0 + 2 * g;
        float2 v0 = unpack2(a0), v1 = unpack2(a1), vr = unpack2(ar);
        Hout[n * OUT + o] = v0.x;        Hout[(n + 1) * OUT + o] = v0.y;
        Hout[(NN + n) * OUT + o] = v1.x; Hout[(NN + n + 1) * OUT + o] = v1.y;
        baseout[n * OUT + o] = vr.x;     baseout[(n + 1) * OUT + o] = vr.y;
    } else {
        // scalar mode (OUT=32)
        float a0 = 0.f, a1 = 0.f, ar = 0.f;
        for (int i = 0; i < IN; i++) {
            float xv = xsT[i][g];
            a0 += xv * wsh[i * OUT + o];
            a1 += xv * wsh[IN * OUT + i * OUT + o];
            ar += xv * __ldg(&root[i * OUT + o]);
        }
        int n = n0 + g;
        Hout[n * OUT + o] = a0;
        Hout[(NN + n) * OUT + o] = a1;
        baseout[n * OUT + o] = ar;
    }
}

// ---------------- fused agg(L3) + GAT projection --------------------------------
__device__ __forceinline__ float lrelu02(float a) { return a > 0.f ? a : 0.2f * a; }

__global__ __launch_bounds__(512) void gat_h_fused(
    const float* __restrict__ Hin, const float* __restrict__ basein,
    const float* __restrict__ bias,
    const int* __restrict__ rowptr, const int* __restrict__ mid,
    const float* __restrict__ inv0, const float* __restrict__ inv1,
    const int* __restrict__ cval,
    const float* __restrict__ gw, const float* __restrict__ ps,
    const float* __restrict__ pd,
    __half* __restrict__ h, float* __restrict__ asv, float* __restrict__ adv) {
    __shared__ __align__(16) float xsT[32][40];
    const int c = threadIdx.x;
    const int wid = c >> 5, lane = c & 31;
    const int n0 = blockIdx.x * 40;

    // phase 1: warp-per-node aggregation of layer-3 output
    for (int m = wid; m < 40; m += 16) {
        int n = n0 + m;
        int e0 = rowptr[n], em = mid[n], e1 = rowptr[n + 1];
        float a0 = agg_range1(Hin, cval, e0, em, lane);
        float a1 = agg_range1(Hin, cval, em, e1, lane);
        xsT[lane][m] = tanhf(basein[n * 32 + lane] + bias[lane]
                             + a0 * inv0[n] + a1 * inv1[n]);
    }
    __syncthreads();

    // phase 2: h = x @ gw (gw column in registers, f32x2 node pairs), fp16 out
    ull gwd[32];
#pragma unroll
    for (int k = 0; k < 32; k++) {
        float g = gw[k * 512 + c];
        gwd[k] = pack2(g, g);
    }
#pragma unroll 4
    for (int mp = 0; mp < 20; mp++) {
        ull acc = 0;
#pragma unroll
        for (int k = 0; k < 32; k++) {
            ull xp = *(const ull*)&xsT[k][2 * mp];
            fma2(acc, xp, gwd[k]);
        }
        float2 v = unpack2(acc);
        h[(size_t)(n0 + 2 * mp) * 512 + c] = __float2half(v.x);
        h[(size_t)(n0 + 2 * mp + 1) * 512 + c] = __float2half(v.y);
    }
    if (c < 40) {
        float s = 0.f, t = 0.f;
#pragma unroll
        for (int k = 0; k < 32; k++) {
            float xv = xsT[k][c];
            s += xv * __ldg(&ps[k]);
            t += xv * __ldg(&pd[k]);
        }
        asv[n0 + c] = s;
        adv[n0 + c] = t;
    }
}

// ---------------- GAT aggregation (softmax + weighted sum, fp16 h) --------------
__global__ void gat_agg_kernel(const __half* __restrict__ h, const float* __restrict__ asv,
                               const float* __restrict__ adv,
                               const int* __restrict__ rowptr, const int* __restrict__ cval,
                               const float* __restrict__ gbias, float* __restrict__ xout) {
    int n = blockIdx.x;
    int t = threadIdx.x;  // 128 threads, 4 fp16 features each
    int e0 = rowptr[n], e1 = rowptr[n + 1];
    float advn = adv[n];
    float aself = lrelu02(asv[n] + advn);
    float lm = aself;
    for (int e = e0 + t; e < e1; e += 128) {
        int o = cval[e];
        int s = (o >= NN) ? o - NN : o;
        lm = fmaxf(lm, lrelu02(asv[s] + advn));
    }
    __shared__ float sred[128];
    sred[t] = lm;
    __syncthreads();
    for (int off = 64; off > 0; off >>= 1) {
        if (t < off) sred[t] = fmaxf(sred[t], sred[t + off]);
        __syncthreads();
    }
    float m = sred[0];
    __shared__ float sEx[128];
    __shared__ int sSrc[128];
    float4 acc = make_float4(0.f, 0.f, 0.f, 0.f);
    float denom = 0.f;
    for (int eb = e0; eb < e1; eb += 128) {
        int cnt = min(128, e1 - eb);
        __syncthreads();
        if (t < cnt) {
            int o = cval[eb + t];
            int s = (o >= NN) ? o - NN : o;
            sSrc[t] = s;
            sEx[t] = expf(lrelu02(asv[s] + advn) - m);
        }
        __syncthreads();
        for (int j = 0; j < cnt; j++) {
            float ex = sEx[j];
            uint2 raw = reinterpret_cast<const uint2*>(h + (size_t)sSrc[j] * 512)[t];
            float2 f0 = __half22float2(*reinterpret_cast<__half2*>(&raw.x));
            float2 f1 = __half22float2(*reinterpret_cast<__half2*>(&raw.y));
            acc.x += ex * f0.x; acc.y += ex * f0.y; acc.z += ex * f1.x; acc.w += ex * f1.y;
            denom += ex;
        }
    }
    float exs = expf(aself - m);
    denom += exs;
    {
        uint2 raw = reinterpret_cast<const uint2*>(h + (size_t)n * 512)[t];
        float2 f0 = __half22float2(*reinterpret_cast<__half2*>(&raw.x));
        float2 f1 = __half22float2(*reinterpret_cast<__half2*>(&raw.y));
        acc.x += exs * f0.x; acc.y += exs * f0.y; acc.z += exs * f1.x; acc.w += exs * f1.y;
    }
    float inv = 1.f / fmaxf(denom, 1e-16f);
    float4 g = reinterpret_cast<const float4*>(gbias)[t];
    float4 o;
    o.x = fmaxf(acc.x * inv + g.x, 0.f);
    o.y = fmaxf(acc.y * inv + g.y, 0.f);
    o.z = fmaxf(acc.z * inv + g.z, 0.f);
    o.w = fmaxf(acc.w * inv + g.w, 0.f);
    reinterpret_cast<float4*>(xout + (size_t)n * 512)[t] = o;
}

// ---------------- edge MLP ------------------------------------------------------
// 256 threads: thread = (col quad cq 0..63) x (pair group pg 0..3, 5 pairs each)
__global__ __launch_bounds__(256) void gemm_ab_kernel(const float* __restrict__ xg,
                                                      const float* __restrict__ w1,
                                                      float* __restrict__ ab) {
    __shared__ __align__(16) float xsT[32][40];
    __shared__ __align__(16) float ws[32][256];
    const int tid = threadIdx.x;
    const int cq = tid & 63;
    const int pg = tid >> 6;
    const int n0 = blockIdx.x * 40;
    ull acc[5][4];
#pragma unroll
    for (int i = 0; i < 5; i++)
#pragma unroll
        for (int j = 0; j < 4; j++) acc[i][j] = 0;

    for (int k0 = 0; k0 < 512; k0 += 32) {
        __syncthreads();
        for (int i = tid; i < 40 * 32; i += 256) {
            int m = i >> 5, kk = i & 31;
            xsT[kk][m] = xg[(size_t)(n0 + m) * 512 + k0 + kk];
        }
        for (int i = tid; i < 32 * 256; i += 256) {
            int kk = i >> 8, cc = i & 255;
            int krow = k0 + kk + ((cc < 128) ? 0 : 512);
            int col = cc & 127;
            ws[kk][cc] = w1[krow * 128 + col];
        }
        __syncthreads();
#pragma unroll 4
        for (int kk = 0; kk < 32; kk++) {
            float4 w = *(const float4*)&ws[kk][4 * cq];
            ull wd0 = pack2(w.x, w.x), wd1 = pack2(w.y, w.y);
            ull wd2 = pack2(w.z, w.z), wd3 = pack2(w.w, w.w);
#pragma unroll
            for (int i = 0; i < 5; i++) {
                ull xp = *(const ull*)&xsT[kk][10 * pg + 2 * i];
                fma2(acc[i][0], xp, wd0);
                fma2(acc[i][1], xp, wd1);
                fma2(acc[i][2], xp, wd2);
                fma2(acc[i][3], xp, wd3);
            }
        }
    }
#pragma unroll
    for (int i = 0; i < 5; i++) {
        int n = n0 + 10 * pg + 2 * i;
        float2 v0 = unpack2(acc[i][0]), v1 = unpack2(acc[i][1]);
        float2 v2 = unpack2(acc[i][2]), v3 = unpack2(acc[i][3]);
        float4 lo = make_float4(v0.x, v1.x, v2.x, v3.x);
        float4 hi = make_float4(v0.y, v1.y, v2.y, v3.y);
        *(float4*)&ab[(size_t)n * 256 + 4 * cq] = lo;
        *(float4*)&ab[(size_t)(n + 1) * 256 + 4 * cq] = hi;
    }
}

__global__ void edge_kernel(const int* __restrict__ ei, const float* __restrict__ ab,
                            const float* __restrict__ b1, const float* __restrict__ w2,
                            const float* __restrict__ b2, float* __restrict__ out) {
    int gid = blockIdx.x * blockDim.x + threadIdx.x;
    int e = gid >> 5;
    int lane = gid & 31;
    if (e >= EE) return;
    int s = ei[e];
    int d = ei[EE + e];
    float4 a = reinterpret_cast<const float4*>(ab + (size_t)s * 256)[lane];
    float4 bv = reinterpret_cast<const float4*>(ab + (size_t)d * 256 + 128)[lane];
    float4 bb = reinterpret_cast<const float4*>(b1)[lane];
    float4 wv = reinterpret_cast<const float4*>(w2)[lane];
    float acc = fmaxf(a.x + bv.x + bb.x, 0.f) * wv.x
              + fmaxf(a.y + bv.y + bb.y, 0.f) * wv.y
              + fmaxf(a.z + bv.z + bb.z, 0.f) * wv.z
              + fmaxf(a.w + bv.w + bb.w, 0.f) * wv.w;
#pragma unroll
    for (int off = 16; off > 0; off >>= 1) acc += __shfl_down_sync(0xffffffffu, acc, off);
    if (lane == 0) out[e] = 1.f / (1.f + expf(-(acc + b2[0])));
}

// ---------------- launch ---------------------------------------------------------
extern "C" void kernel_launch(void* const* d_in, const int* in_sizes, int n_in,
                              void* d_out, int out_size) {
    const float *basis[4], *comp[4], *root[4], *rbias[4];
    const float *gat_w, *att_s, *att_d, *gat_b, *w1, *b1, *w2, *b2;
    const int *ei, *et;

    if (in_sizes[0] == 2 * EE) {
        ei = (const int*)d_in[0];
        et = (const int*)d_in[1];
        int k = 2;
        for (int l = 0; l < 4; l++) {
            basis[l] = (const float*)d_in[k++];
            comp[l]  = (const float*)d_in[k++];
            root[l]  = (const float*)d_in[k++];
            rbias[l] = (const float*)d_in[k++];
        }
        gat_w = (const float*)d_in[18]; att_s = (const float*)d_in[19];
        att_d = (const float*)d_in[20]; gat_b = (const float*)d_in[21];
        w1 = (const float*)d_in[22]; b1 = (const float*)d_in[23];
        w2 = (const float*)d_in[24]; b2 = (const float*)d_in[25];
    } else if (in_sizes[0] == 4 * NN * 32) {
        int k = 0;
        for (int l = 0; l < 4; l++) {
            basis[l] = (const float*)d_in[k++];
            comp[l]  = (const float*)d_in[k++];
            root[l]  = (const float*)d_in[k++];
            rbias[l] = (const float*)d_in[k++];
        }
        gat_w = (const float*)d_in[16]; att_s = (const float*)d_in[17];
        att_d = (const float*)d_in[18]; gat_b = (const float*)d_in[19];
        w1 = (const float*)d_in[20]; b1 = (const float*)d_in[21];
        w2 = (const float*)d_in[22]; b2 = (const float*)d_in[23];
        ei = (const int*)d_in[24]; et = (const int*)d_in[25];
    } else {
        b1 = (const float*)d_in[0]; b2 = (const float*)d_in[1];
        for (int l = 0; l < 4; l++) basis[l] = (const float*)d_in[2 + l];
        for (int l = 0; l < 4; l++) comp[l] = (const float*)d_in[6 + l];
        ei = (const int*)d_in[10]; et = (const int*)d_in[11];
        att_d = (const float*)d_in[12]; att_s = (const float*)d_in[13];
        gat_b = (const float*)d_in[14]; gat_w = (const float*)d_in[15];
        for (int l = 0; l < 4; l++) rbias[l] = (const float*)d_in[16 + l];
        for (int l = 0; l < 4; l++) root[l] = (const float*)d_in[20 + l];
        w1 = (const float*)d_in[24]; w2 = (const float*)d_in[25];
    }

    float *W0, *Ha, *Hb, *baseA, *baseB, *Wr1, *Wr2, *Wr3, *xg, *ab, *asv, *adv, *ps, *pd;
    float *inv0, *inv1;
    __half *h;
    int *deg, *cnt0, *rowptr, *midp, *cursor0, *cursor1, *cval;
    cudaGetSymbolAddress((void**)&W0, g_W0);
    cudaGetSymbolAddress((void**)&Ha, g_Ha);
    cudaGetSymbolAddress((void**)&Hb, g_Hb);
    cudaGetSymbolAddress((void**)&baseA, g_baseA);
    cudaGetSymbolAddress((void**)&baseB, g_baseB);
    cudaGetSymbolAddress((void**)&Wr1, g_Wr1);
    cudaGetSymbolAddress((void**)&Wr2, g_Wr2);
    cudaGetSymbolAddress((void**)&Wr3, g_Wr3);
    cudaGetSymbolAddress((void**)&h, g_h);
    cudaGetSymbolAddress((void**)&xg, g_xg);
    cudaGetSymbolAddress((void**)&ab, g_ab);
    cudaGetSymbolAddress((void**)&asv, g_asv);
    cudaGetSymbolAddress((void**)&adv, g_adv);
    cudaGetSymbolAddress((void**)&ps, g_ps);
    cudaGetSymbolAddress((void**)&pd, g_pd);
    cudaGetSymbolAddress((void**)&inv0, g_inv0);
    cudaGetSymbolAddress((void**)&inv1, g_inv1);
    cudaGetSymbolAddress((void**)&deg, g_deg);
    cudaGetSymbolAddress((void**)&cnt0, g_cnt0);
    cudaGetSymbolAddress((void**)&rowptr, g_rowptr);
    cudaGetSymbolAddress((void**)&midp, g_mid);
    cudaGetSymbolAddress((void**)&cursor0, g_cursor0);
    cudaGetSymbolAddress((void**)&cursor1, g_cursor1);
    cudaGetSymbolAddress((void**)&cval, g_cval);

    float* out = (float*)d_out;

    // 1) persistent prep + CSR build
    csr_prep_kernel<<<NB, 256>>>(
        basis[0], comp[0], basis[1], comp[1], basis[2], comp[2], basis[3], comp[3],
        gat_w, att_s, att_d, ei, et,
        W0, Wr1, Wr2, Wr3, deg, cnt0, rowptr, midp, cursor0, cursor1,
        inv0, inv1, cval, ps, pd);

    // 2-4) fused agg(L) + dense(L+1)
    fused_agg_dense<32, 64><<<NN / 16, 512>>>(W0, root[0], rbias[0], rowptr, midp,
                                              inv0, inv1, cval, Wr1, root[1], Ha, baseA);
    fused_agg_dense<64, 64><<<NN / 16, 512>>>(Ha, baseA, rbias[1], rowptr, midp,
                                              inv0, inv1, cval, Wr2, root[2], Hb, baseB);
    fused_agg_dense<64, 32><<<NN / 16, 512>>>(Hb, baseB, rbias[2], rowptr, midp,
                                              inv0, inv1, cval, Wr3, root[3], Ha, baseA);

    // 5) fused agg(L3) + GAT projection (fp16 h out)
    gat_h_fused<<<NN / 40, 512>>>(Ha, baseA, rbias[3], rowptr, midp, inv0, inv1, cval,
                                  gat_w, ps, pd, h, asv, adv);

    // 6) GAT softmax aggregation
    gat_agg_kernel<<<NN, 128>>>(h, asv, adv, rowptr, cval, gat_b, xg);

    // 7) edge-MLP node GEMM (factorized feat@w1 = A[src]+B[dst])
    gemm_ab_kernel<<<NN / 40, 256>>>(xg, w1, ab);

    // 8) per-edge MLP tail
    edge_kernel<<<(EE * 32 + 255) / 256, 256>>>(ei, ab, b1, w2, b2, out);
}

// round 7
// speedup vs baseline: 1.5155x; 1.5155x over previous
#include <cuda_runtime.h>
#include <cuda_fp16.h>
#include <math.h>

#define NN 6000
#define EE 100000

typedef unsigned long long ull;

// ---------------- f32x2 packed-FMA helpers (sm_103a FFMA2) ----------------------
__device__ __forceinline__ void fma2(ull& d, ull a, ull b) {
    asm("fma.rn.f32x2 %0, %1, %2, %0;" : "+l"(d) : "l"(a), "l"(b));
}
__device__ __forceinline__ ull pack2(float lo, float hi) {
    ull r; asm("mov.b64 %0, {%1, %2};" : "=l"(r) : "f"(lo), "f"(hi)); return r;
}
__device__ __forceinline__ float2 unpack2(ull v) {
    float2 r; asm("mov.b64 {%0, %1}, %2;" : "=f"(r.x), "=f"(r.y) : "l"(v)); return r;
}

// ---------------- scratch (device globals; no allocations allowed) -------------
__device__ float  g_H[2 * NN * 64];    // per-relation H matrices (holds W0 for layer 0)
__device__ float  g_base[NN * 64];     // x @ root
__device__ float  g_xA[NN * 64];
__device__ float  g_xB[NN * 64];
__device__ float  g_Wr1[2 * 32 * 64];
__device__ float  g_Wr2[2 * 64 * 64];
__device__ float  g_Wr3[2 * 64 * 32];
__device__ __half g_h[NN * 512];       // GAT projected features (fp16)
__device__ float  g_xg[NN * 512];      // GAT output
__device__ float  g_ab[NN * 256];      // [A | B] for edge MLP
__device__ float  g_asv[NN];
__device__ float  g_adv[NN];
__device__ float  g_ps[32];
__device__ float  g_pd[32];
__device__ float  g_cnt[NN * 2];       // per-relation in-counts (float)
__device__ int    g_deg[NN];
__device__ int    g_rowptr[NN + 1];
__device__ int    g_cursor[NN];
__device__ int    g_csrc[EE];
__device__ int    g_ctype[EE];

// ---------------- prep: zero + all wcomp + projected attention vectors ----------
#define PREP_TOTAL (384000 + 4096 + 8192 + 4096 + 18000 + 2048)

__global__ void prep_kernel(const float* __restrict__ basis0, const float* __restrict__ comp0,
                            const float* __restrict__ basis1, const float* __restrict__ comp1,
                            const float* __restrict__ basis2, const float* __restrict__ comp2,
                            const float* __restrict__ basis3, const float* __restrict__ comp3,
                            const float* __restrict__ gw, const float* __restrict__ a_s,
                            const float* __restrict__ a_d,
                            float* __restrict__ W0, float* __restrict__ Wr1,
                            float* __restrict__ Wr2, float* __restrict__ Wr3,
                            int* __restrict__ deg, float* __restrict__ cnt,
                            float* __restrict__ ps, float* __restrict__ pd) {
    int idx = blockIdx.x * blockDim.x + threadIdx.x;
    if (idx < 384000) {
        int r = idx / 192000, io = idx - r * 192000;
        float s = 0.f;
#pragma unroll
        for (int b = 0; b < 4; b++) s += comp0[r * 4 + b] * basis0[b * 192000 + io];
        W0[idx] = s;
        return;
    }
    idx -= 384000;
    if (idx < 4096) {
        int r = idx / 2048, io = idx - r * 2048;
        float s = 0.f;
#pragma unroll
        for (int b = 0; b < 4; b++) s += comp1[r * 4 + b] * basis1[b * 2048 + io];
        Wr1[idx] = s;
        return;
    }
    idx -= 4096;
    if (idx < 8192) {
        int r = idx / 4096, io = idx - r * 4096;
        float s = 0.f;
#pragma unroll
        for (int b = 0; b < 4; b++) s += comp2[r * 4 + b] * basis2[b * 4096 + io];
        Wr2[idx] = s;
        return;
    }
    idx -= 8192;
    if (idx < 4096) {
        int r = idx / 2048, io = idx - r * 2048;
        float s = 0.f;
#pragma unroll
        for (int b = 0; b < 4; b++) s += comp3[r * 4 + b] * basis3[b * 2048 + io];
        Wr3[idx] = s;
        return;
    }
    idx -= 4096;
    if (idx < 18000) {
        if (idx < 6000) deg[idx] = 0;
        else cnt[idx - 6000] = 0.f;
        return;
    }
    idx -= 18000;
    if (idx < 2048) {
        int w = idx >> 5, lane = idx & 31;
        int i = w & 31;
        const float* a = (w < 32) ? a_s : a_d;
        float s = 0.f;
        for (int c = lane; c < 512; c += 32) s += gw[i * 512 + c] * a[c];
#pragma unroll
        for (int off = 16; off > 0; off >>= 1) s += __shfl_down_sync(0xffffffffu, s, off);
        if (lane == 0) { if (w < 32) ps[i] = s; else pd[i] = s; }
    }
}

// ---------------- CSR build ----------------------------------------------------
__global__ void count_kernel(const int* __restrict__ ei, const int* __restrict__ et,
                             int* deg, float* cnt) {
    int e = blockIdx.x * blockDim.x + threadIdx.x;
    if (e >= EE) return;
    int d = ei[EE + e];
    atomicAdd(&deg[d], 1);
    atomicAdd(&cnt[d * 2 + et[e]], 1.0f);
}

__global__ void scan_kernel(const int* __restrict__ deg, int* rowptr, int* cursor) {
    int t = threadIdx.x;  // 1024
    int base = t * 6;
    int loc[6];
    int sum = 0;
#pragma unroll
    for (int i = 0; i < 6; i++) {
        int idx = base + i;
        int v = (idx < NN) ? deg[idx] : 0;
        loc[i] = sum;
        sum += v;
    }
    int lane = t & 31, w = t >> 5;
    int v = sum;
#pragma unroll
    for (int off = 1; off < 32; off <<= 1) {
        int n = __shfl_up_sync(0xffffffffu, v, off);
        if (lane >= off) v += n;
    }
    __shared__ int wsum[32];
    if (lane == 31) wsum[w] = v;
    __syncthreads();
    if (w == 0) {
        int x = wsum[lane];
#pragma unroll
        for (int off = 1; off < 32; off <<= 1) {
            int n = __shfl_up_sync(0xffffffffu, x, off);
            if (lane >= off) x += n;
        }
        wsum[lane] = x;
    }
    __syncthreads();
    int incl = v + (w > 0 ? wsum[w - 1] : 0);
    int excl = incl - sum;
#pragma unroll
    for (int i = 0; i < 6; i++) {
        int idx = base + i;
        if (idx < NN) { rowptr[idx] = excl + loc[i]; cursor[idx] = excl + loc[i]; }
    }
    if (t == 1023) rowptr[NN] = incl;
}

__global__ void fill_kernel(const int* __restrict__ ei, const int* __restrict__ et,
                            int* cursor, int* csrc, int* ctype) {
    int e = blockIdx.x * blockDim.x + threadIdx.x;
    if (e >= EE) return;
    int s = ei[e];
    int d = ei[EE + e];
    int pos = atomicAdd(&cursor[d], 1);
    csrc[pos] = s;
    ctype[pos] = et[e];
}

// ---------------- RGCN ---------------------------------------------------------
// H[r] = x @ Wr[r], base = x @ root. Block: 256 threads, M=16 nodes.
template<int IN, int OUT>
__global__ __launch_bounds__(256) void dense_rgcn(const float* __restrict__ x,
                                                  const float* __restrict__ Wr,
                                                  const float* __restrict__ root,
                                                  float* __restrict__ H, float* __restrict__ base) {
    constexpr int M = 16;
    constexpr int G = 256 / OUT;       // groups of OUT threads
    constexpr int P = (M / 2) / G;     // node-pairs per thread
    __shared__ float wsh[2 * IN * OUT];
    __shared__ float xsT[IN][M];
    const int tid = threadIdx.x;
    const int n0 = blockIdx.x * M;
    for (int i = tid; i < IN * OUT; i += 256) {
        wsh[i] = Wr[i];
        wsh[IN * OUT + i] = Wr[IN * OUT + i];
    }
    for (int i = tid; i < M * IN; i += 256) {
        int m = i / IN, k = i - m * IN;
        xsT[k][m] = x[(n0 + m) * IN + k];
    }
    __syncthreads();
    const int o = tid & (OUT - 1);
    const int g = tid / OUT;
    ull a0[P], a1[P], ar[P];
#pragma unroll
    for (int p = 0; p < P; p++) { a0[p] = 0; a1[p] = 0; ar[p] = 0; }
    for (int i = 0; i < IN; i++) {
        float w0 = wsh[i * OUT + o];
        float w1 = wsh[IN * OUT + i * OUT + o];
        float wr = __ldg(&root[i * OUT + o]);
        ull w0d = pack2(w0, w0), w1d = pack2(w1, w1), wrd = pack2(wr, wr);
#pragma unroll
        for (int p = 0; p < P; p++) {
            ull xp = *(const ull*)&xsT[i][2 * (g * P + p)];
            fma2(a0[p], xp, w0d);
            fma2(a1[p], xp, w1d);
            fma2(ar[p], xp, wrd);
        }
    }
#pragma unroll
    for (int p = 0; p < P; p++) {
        int n = n0 + 2 * (g * P + p);
        float2 v0 = unpack2(a0[p]), v1 = unpack2(a1[p]), vr = unpack2(ar[p]);
        H[n * OUT + o] = v0.x;       H[(n + 1) * OUT + o] = v0.y;
        H[(NN + n) * OUT + o] = v1.x; H[(NN + n + 1) * OUT + o] = v1.y;
        base[n * OUT + o] = vr.x;     base[(n + 1) * OUT + o] = vr.y;
    }
}

// per-node per-relation mean aggregation + tanh (unroll-4 edge walk)
__global__ void agg_rgcn(const float* __restrict__ H, const float* __restrict__ base,
                         const float* __restrict__ bias, const float* __restrict__ cnt,
                         const int* __restrict__ rowptr, const int* __restrict__ csrc,
                         const int* __restrict__ ctype,
                         float* __restrict__ xout, int out) {
    int m = threadIdx.y;
    int n = blockIdx.x * blockDim.y + m;
    int o = threadIdx.x;
    float a0 = 0.f, a1 = 0.f;
    int e0 = rowptr[n], e1 = rowptr[n + 1];
    int e = e0;
    for (; e + 4 <= e1; e += 4) {
        int s0 = csrc[e],     s1 = csrc[e + 1], s2 = csrc[e + 2], s3 = csrc[e + 3];
        int t0 = ctype[e],    t1 = ctype[e + 1], t2 = ctype[e + 2], t3 = ctype[e + 3];
        float v0 = H[(t0 * NN + s0) * out + o];
        float v1 = H[(t1 * NN + s1) * out + o];
        float v2 = H[(t2 * NN + s2) * out + o];
        float v3 = H[(t3 * NN + s3) * out + o];
        if (t0) a1 += v0; else a0 += v0;
        if (t1) a1 += v1; else a0 += v1;
        if (t2) a1 += v2; else a0 += v2;
        if (t3) a1 += v3; else a0 += v3;
    }
    for (; e < e1; e++) {
        int s = csrc[e];
        int t = ctype[e];
        float v = H[(t * NN + s) * out + o];
        if (t) a1 += v; else a0 += v;
    }
    float c0 = fmaxf(cnt[n * 2 + 0], 1.f);
    float c1 = fmaxf(cnt[n * 2 + 1], 1.f);
    xout[n * out + o] = tanhf(base[n * out + o] + bias[o] + a0 / c0 + a1 / c1);
}

// ---------------- GAT ----------------------------------------------------------
__device__ __forceinline__ float lrelu02(float a) { return a > 0.f ? a : 0.2f * a; }

// Block: 512 threads (cols), M=40 nodes; gw column cached in registers,
// asv/adv via precomputed p_s/p_d 32-vectors. fp16 h output.
__global__ __launch_bounds__(512) void gat_h_kernel(const float* __restrict__ x,
                                                    const float* __restrict__ gw,
                                                    const float* __restrict__ ps,
                                                    const float* __restrict__ pd,
                                                    __half* __restrict__ h,
                                                    float* __restrict__ asv, float* __restrict__ adv) {
    __shared__ float xsT[32][40];
    const int c = threadIdx.x;
    const int n0 = blockIdx.x * 40;
    for (int i = c; i < 40 * 32; i += 512) {
        int m = i >> 5, k = i & 31;
        xsT[k][m] = x[(n0 + m) * 32 + k];
    }
    __syncthreads();
    ull gwd[32];
#pragma unroll
    for (int k = 0; k < 32; k++) {
        float g = gw[k * 512 + c];
        gwd[k] = pack2(g, g);
    }
#pragma unroll 4
    for (int mp = 0; mp < 20; mp++) {
        ull acc = 0;
#pragma unroll
        for (int k = 0; k < 32; k++) {
            ull xp = *(const ull*)&xsT[k][2 * mp];
            fma2(acc, xp, gwd[k]);
        }
        float2 v = unpack2(acc);
        h[(size_t)(n0 + 2 * mp) * 512 + c] = __float2half(v.x);
        h[(size_t)(n0 + 2 * mp + 1) * 512 + c] = __float2half(v.y);
    }
    if (c < 40) {
        float s = 0.f, t = 0.f;
#pragma unroll
        for (int k = 0; k < 32; k++) {
            float xv = xsT[k][c];
            s += xv * __ldg(&ps[k]);
            t += xv * __ldg(&pd[k]);
        }
        asv[n0 + c] = s;
        adv[n0 + c] = t;
    }
}

__global__ void gat_agg_kernel(const __half* __restrict__ h, const float* __restrict__ asv,
                               const float* __restrict__ adv,
                               const int* __restrict__ rowptr, const int* __restrict__ csrc,
                               const float* __restrict__ gbias, float* __restrict__ xout) {
    int n = blockIdx.x;
    int t = threadIdx.x;  // 128 threads, 4 fp16 features each
    int e0 = rowptr[n], e1 = rowptr[n + 1];
    float advn = adv[n];
    float aself = lrelu02(asv[n] + advn);
    // pass 1: max
    float lm = aself;
    for (int e = e0 + t; e < e1; e += 128) lm = fmaxf(lm, lrelu02(asv[csrc[e]] + advn));
    __shared__ float sred[128];
    sred[t] = lm;
    __syncthreads();
    for (int off = 64; off > 0; off >>= 1) {
        if (t < off) sred[t] = fmaxf(sred[t], sred[t + off]);
        __syncthreads();
    }
    float m = sred[0];
    // pass 2: exp staged in shared (one exp per edge), accumulate
    __shared__ float sEx[128];
    __shared__ int sSrc[128];
    float4 acc = make_float4(0.f, 0.f, 0.f, 0.f);
    float denom = 0.f;
    for (int eb = e0; eb < e1; eb += 128) {
        int cnt = min(128, e1 - eb);
        __syncthreads();
        if (t < cnt) {
            int s = csrc[eb + t];
            sSrc[t] = s;
            sEx[t] = expf(lrelu02(asv[s] + advn) - m);
        }
        __syncthreads();
        for (int j = 0; j < cnt; j++) {
            float ex = sEx[j];
            uint2 raw = reinterpret_cast<const uint2*>(h + (size_t)sSrc[j] * 512)[t];
            float2 f0 = __half22float2(*reinterpret_cast<__half2*>(&raw.x));
            float2 f1 = __half22float2(*reinterpret_cast<__half2*>(&raw.y));
            acc.x += ex * f0.x; acc.y += ex * f0.y; acc.z += ex * f1.x; acc.w += ex * f1.y;
            denom += ex;
        }
    }
    // self loop
    float exs = expf(aself - m);
    denom += exs;
    {
        uint2 raw = reinterpret_cast<const uint2*>(h + (size_t)n * 512)[t];
        float2 f0 = __half22float2(*reinterpret_cast<__half2*>(&raw.x));
        float2 f1 = __half22float2(*reinterpret_cast<__half2*>(&raw.y));
        acc.x += exs * f0.x; acc.y += exs * f0.y; acc.z += exs * f1.x; acc.w += exs * f1.y;
    }
    float inv = 1.f / fmaxf(denom, 1e-16f);
    float4 g = reinterpret_cast<const float4*>(gbias)[t];
    float4 o;
    o.x = fmaxf(acc.x * inv + g.x, 0.f);
    o.y = fmaxf(acc.y * inv + g.y, 0.f);
    o.z = fmaxf(acc.z * inv + g.z, 0.f);
    o.w = fmaxf(acc.w * inv + g.w, 0.f);
    reinterpret_cast<float4*>(xout + (size_t)n * 512)[t] = o;
}

// ---------------- edge MLP ------------------------------------------------------
// AB[n,0:128] = xg[n] @ w1[0:512,:]; AB[n,128:256] = xg[n] @ w1[512:1024,:]
// Block: 256 threads (cols), M=40 nodes, f32x2 node-pair accumulators.
__global__ __launch_bounds__(256) void gemm_ab_kernel(const float* __restrict__ xg,
                                                      const float* __restrict__ w1,
                                                      float* __restrict__ ab) {
    __shared__ float xsT[32][40];
    __shared__ float ws[32][256];
    const int c = threadIdx.x;
    const int n0 = blockIdx.x * 40;
    ull acc[20];
#pragma unroll
    for (int p = 0; p < 20; p++) acc[p] = 0;
    for (int k0 = 0; k0 < 512; k0 += 32) {
        __syncthreads();
        for (int i = c; i < 40 * 32; i += 256) {
            int m = i >> 5, kk = i & 31;
            xsT[kk][m] = xg[(size_t)(n0 + m) * 512 + k0 + kk];
        }
        for (int i = c; i < 32 * 256; i += 256) {
            int kk = i >> 8, cc = i & 255;
            int krow = k0 + kk + ((cc < 128) ? 0 : 512);
            int col = cc & 127;
            ws[kk][cc] = w1[krow * 128 + col];
        }
        __syncthreads();
#pragma unroll 8
        for (int kk = 0; kk < 32; kk++) {
            float wv = ws[kk][c];
            ull wd = pack2(wv, wv);
            const float* xr = &xsT[kk][0];
#pragma unroll
            for (int p = 0; p < 20; p++) {
                ull xp = *(const ull*)(xr + 2 * p);
                fma2(acc[p], xp, wd);
            }
        }
    }
#pragma unroll
    for (int p = 0; p < 20; p++) {
        float2 v = unpack2(acc[p]);
        ab[(size_t)(n0 + 2 * p) * 256 + c] = v.x;
        ab[(size_t)(n0 + 2 * p + 1) * 256 + c] = v.y;
    }
}

// warp per edge: out = sigmoid( relu(A[src]+B[dst]+b1) . w2 + b2 )
__global__ void edge_kernel(const int* __restrict__ ei, const float* __restrict__ ab,
                            const float* __restrict__ b1, const float* __restrict__ w2,
                            const float* __restrict__ b2, float* __restrict__ out) {
    int gid = blockIdx.x * blockDim.x + threadIdx.x;
    int e = gid >> 5;
    int lane = gid & 31;
    if (e >= EE) return;
    int s = ei[e];
    int d = ei[EE + e];
    float4 a = reinterpret_cast<const float4*>(ab + (size_t)s * 256)[lane];
    float4 bv = reinterpret_cast<const float4*>(ab + (size_t)d * 256 + 128)[lane];
    float4 bb = reinterpret_cast<const float4*>(b1)[lane];
    float4 wv = reinterpret_cast<const float4*>(w2)[lane];
    float acc = fmaxf(a.x + bv.x + bb.x, 0.f) * wv.x
              + fmaxf(a.y + bv.y + bb.y, 0.f) * wv.y
              + fmaxf(a.z + bv.z + bb.z, 0.f) * wv.z
              + fmaxf(a.w + bv.w + bb.w, 0.f) * wv.w;
#pragma unroll
    for (int off = 16; off > 0; off >>= 1) acc += __shfl_down_sync(0xffffffffu, acc, off);
    if (lane == 0) out[e] = 1.f / (1.f + expf(-(acc + b2[0])));
}

// ---------------- launch ---------------------------------------------------------
extern "C" void kernel_launch(void* const* d_in, const int* in_sizes, int n_in,
                              void* d_out, int out_size) {
    const float *basis[4], *comp[4], *root[4], *rbias[4];
    const float *gat_w, *att_s, *att_d, *gat_b, *w1, *b1, *w2, *b2;
    const int *ei, *et;

    if (in_sizes[0] == 2 * EE) {
        ei = (const int*)d_in[0];
        et = (const int*)d_in[1];
        int k = 2;
        for (int l = 0; l < 4; l++) {
            basis[l] = (const float*)d_in[k++];
            comp[l]  = (const float*)d_in[k++];
            root[l]  = (const float*)d_in[k++];
            rbias[l] = (const float*)d_in[k++];
        }
        gat_w = (const float*)d_in[18]; att_s = (const float*)d_in[19];
        att_d = (const float*)d_in[20]; gat_b = (const float*)d_in[21];
        w1 = (const float*)d_in[22]; b1 = (const float*)d_in[23];
        w2 = (const float*)d_in[24]; b2 = (const float*)d_in[25];
    } else if (in_sizes[0] == 4 * NN * 32) {
        int k = 0;
        for (int l = 0; l < 4; l++) {
            basis[l] = (const float*)d_in[k++];
            comp[l]  = (const float*)d_in[k++];
            root[l]  = (const float*)d_in[k++];
            rbias[l] = (const float*)d_in[k++];
        }
        gat_w = (const float*)d_in[16]; att_s = (const float*)d_in[17];
        att_d = (const float*)d_in[18]; gat_b = (const float*)d_in[19];
        w1 = (const float*)d_in[20]; b1 = (const float*)d_in[21];
        w2 = (const float*)d_in[22]; b2 = (const float*)d_in[23];
        ei = (const int*)d_in[24]; et = (const int*)d_in[25];
    } else {
        b1 = (const float*)d_in[0]; b2 = (const float*)d_in[1];
        for (int l = 0; l < 4; l++) basis[l] = (const float*)d_in[2 + l];
        for (int l = 0; l < 4; l++) comp[l] = (const float*)d_in[6 + l];
        ei = (const int*)d_in[10]; et = (const int*)d_in[11];
        att_d = (const float*)d_in[12]; att_s = (const float*)d_in[13];
        gat_b = (const float*)d_in[14]; gat_w = (const float*)d_in[15];
        for (int l = 0; l < 4; l++) rbias[l] = (const float*)d_in[16 + l];
        for (int l = 0; l < 4; l++) root[l] = (const float*)d_in[20 + l];
        w1 = (const float*)d_in[24]; w2 = (const float*)d_in[25];
    }

    float *H, *base, *xA, *xB, *Wr1, *Wr2, *Wr3, *xg, *ab, *asv, *adv, *cnt, *ps, *pd;
    __half *h;
    int *deg, *rowptr, *cursor, *csrc, *ctype;
    cudaGetSymbolAddress((void**)&H, g_H);
    cudaGetSymbolAddress((void**)&base, g_base);
    cudaGetSymbolAddress((void**)&xA, g_xA);
    cudaGetSymbolAddress((void**)&xB, g_xB);
    cudaGetSymbolAddress((void**)&Wr1, g_Wr1);
    cudaGetSymbolAddress((void**)&Wr2, g_Wr2);
    cudaGetSymbolAddress((void**)&Wr3, g_Wr3);
    cudaGetSymbolAddress((void**)&h, g_h);
    cudaGetSymbolAddress((void**)&xg, g_xg);
    cudaGetSymbolAddress((void**)&ab, g_ab);
    cudaGetSymbolAddress((void**)&asv, g_asv);
    cudaGetSymbolAddress((void**)&adv, g_adv);
    cudaGetSymbolAddress((void**)&ps, g_ps);
    cudaGetSymbolAddress((void**)&pd, g_pd);
    cudaGetSymbolAddress((void**)&cnt, g_cnt);
    cudaGetSymbolAddress((void**)&deg, g_deg);
    cudaGetSymbolAddress((void**)&rowptr, g_rowptr);
    cudaGetSymbolAddress((void**)&cursor, g_cursor);
    cudaGetSymbolAddress((void**)&csrc, g_csrc);
    cudaGetSymbolAddress((void**)&ctype, g_ctype);

    float* out = (float*)d_out;

    // ---- fused prep (zero + all basis combinations + p_s/p_d) ----
    prep_kernel<<<(PREP_TOTAL + 255) / 256, 256>>>(
        basis[0], comp[0], basis[1], comp[1], basis[2], comp[2], basis[3], comp[3],
        gat_w, att_s, att_d, H, Wr1, Wr2, Wr3, deg, cnt, ps, pd);

    // ---- CSR build ----
    count_kernel<<<(EE + 255) / 256, 256>>>(ei, et, deg, cnt);
    scan_kernel<<<1, 1024>>>(deg, rowptr, cursor);
    fill_kernel<<<(EE + 255) / 256, 256>>>(ei, et, cursor, csrc, ctype);

    // ---- Layer 0 (x = I shortcut): H = W0, base = root0 ----
    agg_rgcn<<<NN / 8, dim3(32, 8)>>>(H, root[0], rbias[0], cnt, rowptr, csrc, ctype, xA, 32);

    // ---- Layer 1: 32 -> 64 ----
    dense_rgcn<32, 64><<<NN / 16, 256>>>(xA, Wr1, root[1], H, base);
    agg_rgcn<<<NN / 4, dim3(64, 4)>>>(H, base, rbias[1], cnt, rowptr, csrc, ctype, xB, 64);

    // ---- Layer 2: 64 -> 64 ----
    dense_rgcn<64, 64><<<NN / 16, 256>>>(xB, Wr2, root[2], H, base);
    agg_rgcn<<<NN / 4, dim3(64, 4)>>>(H, base, rbias[2], cnt, rowptr, csrc, ctype, xA, 64);

    // ---- Layer 3: 64 -> 32 ----
    dense_rgcn<64, 32><<<NN / 16, 256>>>(xA, Wr3, root[3], H, base);
    agg_rgcn<<<NN / 8, dim3(32, 8)>>>(H, base, rbias[3], cnt, rowptr, csrc, ctype, xB, 32);

    // ---- GAT ----
    gat_h_kernel<<<NN / 40, 512>>>(xB, gat_w, ps, pd, h, asv, adv);
    gat_agg_kernel<<<NN, 128>>>(h, asv, adv, rowptr, csrc, gat_b, xg);

    // ---- edge MLP (factorized: feat@w1 = A[src]+B[dst]) ----
    gemm_ab_kernel<<<NN / 40, 256>>>(xg, w1, ab);
    edge_kernel<<<(EE * 32 + 255) / 256, 256>>>(ei, ab, b1, w2, b2, out);
}